// round 5
// baseline (speedup 1.0000x reference)
#include <cuda_runtime.h>
#include <cuda_bf16.h>
#include <cstdint>

// Problem shape (fixed by the dataset)
#define T_TOK 8192
#define K_IN  4096
#define N_OUT 4096
#define GROUP 32

// Dequantized scratch (bf16 is exact for MXFP4 values)
__device__ __nv_bfloat16 g_xq[(size_t)T_TOK * K_IN];   // 64 MB
__device__ __nv_bfloat16 g_wq[(size_t)N_OUT * K_IN];   // 32 MB

// ---------------------------------------------------------------------------
// Kernel 1: Hadamard rotate + MXFP4 qdq. One thread per 32-elem group,
// FWHT fully in registers, 8x LDG.128 in, 4x STG.128 out.
// ---------------------------------------------------------------------------
#define XGRP ((long long)T_TOK * K_IN / GROUP)
#define TGRP (XGRP + (long long)N_OUT * K_IN / GROUP)

__global__ __launch_bounds__(256)
void rotate_quant_kernel(const float4* __restrict__ x4,
                         const float4* __restrict__ w4,
                         uint4* __restrict__ xq4,
                         uint4* __restrict__ wq4) {
    long long g = (long long)blockIdx.x * blockDim.x + threadIdx.x;
    if (g >= TGRP) return;

    const float4* src;
    uint4* dst;
    if (g < XGRP) { src = x4 + g * 8;          dst = xq4 + g * 4; }
    else          { src = w4 + (g - XGRP) * 8; dst = wq4 + (g - XGRP) * 4; }

    float v[32];
    #pragma unroll
    for (int i = 0; i < 8; i++) {
        float4 t = src[i];
        v[4 * i] = t.x; v[4 * i + 1] = t.y; v[4 * i + 2] = t.z; v[4 * i + 3] = t.w;
    }

    #pragma unroll
    for (int st = 1; st < 32; st <<= 1) {
        #pragma unroll
        for (int i = 0; i < 32; i++) {
            if (!(i & st)) {
                float a = v[i], b = v[i | st];
                v[i] = a + b; v[i | st] = a - b;
            }
        }
    }
    const float c = 0.17677669529663688f;   // 1/sqrt(32)
    float amax = 0.0f;
    #pragma unroll
    for (int i = 0; i < 32; i++) { v[i] *= c; amax = fmaxf(amax, fabsf(v[i])); }
    amax = fmaxf(amax, 1.1754943508222875e-38f);

    int e = (int)((__float_as_uint(amax) >> 23) & 0xFF) - 127 - 2;
    e = max(-127, min(127, e));
    const float scale  = ldexpf(1.0f, e);
    const float iscale = ldexpf(1.0f, -e);

    uint32_t wbuf[16];
    #pragma unroll
    for (int i = 0; i < 32; i += 2) {
        uint32_t pk = 0;
        #pragma unroll
        for (int r = 0; r < 2; r++) {
            float s = v[i + r] * iscale;
            float a = fminf(fabsf(s), 6.0f);
            float q;
            if (a > 2.5f)       q = (a > 5.0f)  ? 6.0f : ((a > 3.5f)  ? 4.0f : 3.0f);
            else if (a > 1.25f) q = (a > 1.75f) ? 2.0f : 1.5f;
            else                q = (a > 0.75f) ? 1.0f : ((a > 0.25f) ? 0.5f : 0.0f);
            float res = copysignf(q, s) * scale;
            pk |= (uint32_t)__bfloat16_as_ushort(__float2bfloat16(res)) << (16 * r);
        }
        wbuf[i >> 1] = pk;
    }
    #pragma unroll
    for (int i = 0; i < 4; i++)
        dst[i] = make_uint4(wbuf[4 * i], wbuf[4 * i + 1], wbuf[4 * i + 2], wbuf[4 * i + 3]);
}

// ---------------------------------------------------------------------------
// Kernel 2: bf16 GEMM  C[M,N] = A[M,K] @ B[N,K]^T + bias, fp32 accumulate.
// 128x256 CTA tile, 256 threads (8 warps, 2x4), warp tile 64x64.
// BK=64 (128B rows), 4-stage cp.async (unrolled: stage offsets are
// compile-time), ldmatrix.x4 fragments.
// ---------------------------------------------------------------------------
#define BM 128
#define BN 256
#define BK 64
#define NSTG 4
#define LDE 72                          // bf16 per smem row (16B pad)
#define ROWB (LDE * 2)                  // 144 bytes
#define A_BYTES (BM * ROWB)             // 18432
#define B_BYTES (BN * ROWB)             // 36864
#define STG_B (A_BYTES + B_BYTES)       // 55296
#define MI_STEP (16 * ROWB)             // 2304 bytes per 16 rows
#define SMEM_BYTES (NSTG * STG_B + 1024)

__device__ __forceinline__ uint32_t smem_u32(const void* p) {
    uint32_t a;
    asm("{ .reg .u64 t; cvta.to.shared.u64 t, %1; cvt.u32.u64 %0, t; }"
        : "=r"(a) : "l"(p));
    return a;
}
#define LDSM4(r0, r1, r2, r3, addr)                                           \
    asm volatile("ldmatrix.sync.aligned.m8n8.x4.shared.b16 {%0,%1,%2,%3}, [%4];" \
                 : "=r"(r0), "=r"(r1), "=r"(r2), "=r"(r3) : "r"(addr))
#define MMA16816(c, a0, a1, a2, a3, b0, b1)                                   \
    asm volatile("mma.sync.aligned.m16n8k16.row.col.f32.bf16.bf16.f32 "       \
                 "{%0,%1,%2,%3},{%4,%5,%6,%7},{%8,%9},{%0,%1,%2,%3};"          \
                 : "+f"(c[0]), "+f"(c[1]), "+f"(c[2]), "+f"(c[3])              \
                 : "r"(a0), "r"(a1), "r"(a2), "r"(a3), "r"(b0), "r"(b1))

__global__ __launch_bounds__(256, 1)
void gemm_bf16_kernel(const __nv_bfloat16* __restrict__ A,
                      const __nv_bfloat16* __restrict__ B,
                      const float* __restrict__ bias,
                      float* __restrict__ C) {
    extern __shared__ char smem[];
    const uint32_t sbase = smem_u32(smem);
    float* sBias = (float*)(smem + NSTG * STG_B);

    const int tid = threadIdx.x;
    const int bm = blockIdx.y, bn = blockIdx.x;
    const int warp = tid >> 5, lane = tid & 31;
    const int wm = warp >> 2;           // 0..1, 64 rows each
    const int wn = warp & 3;            // 0..3, 64 cols each

    sBias[tid] = bias[bn * BN + tid];

    // --- cp.async task setup: 12 x 16B per thread per stage ---
    const __nv_bfloat16* Ab = A + (size_t)bm * BM * K_IN;
    const __nv_bfloat16* Bb = B + (size_t)bn * BN * K_IN;
    uint32_t dA[4]; const char* sAp[4];
    #pragma unroll
    for (int i = 0; i < 4; i++) {
        int idx = tid + i * 256;        // 0..1023
        int row = idx >> 3, cc = idx & 7;
        dA[i] = row * ROWB + cc * 16;
        sAp[i] = (const char*)(Ab + (size_t)row * K_IN) + cc * 16;
    }
    uint32_t dB[8]; const char* sBp[8];
    #pragma unroll
    for (int j = 0; j < 8; j++) {
        int idx = tid + j * 256;        // 0..2047
        int row = idx >> 3, cc = idx & 7;
        dB[j] = A_BYTES + row * ROWB + cc * 16;
        sBp[j] = (const char*)(Bb + (size_t)row * K_IN) + cc * 16;
    }

    auto load_stage = [&](uint32_t off) {
        uint32_t base = sbase + off;
        #pragma unroll
        for (int i = 0; i < 4; i++) {
            asm volatile("cp.async.cg.shared.global [%0], [%1], 16;"
                         :: "r"(base + dA[i]), "l"(sAp[i]));
            sAp[i] += BK * 2;
        }
        #pragma unroll
        for (int j = 0; j < 8; j++) {
            asm volatile("cp.async.cg.shared.global [%0], [%1], 16;"
                         :: "r"(base + dB[j]), "l"(sBp[j]));
            sBp[j] += BK * 2;
        }
        asm volatile("cp.async.commit_group;");
    };

    // --- fragment base addresses (hoisted, stage offset added as constant) ---
    const uint32_t aBase = sbase + (wm * 64 + (lane & 15)) * ROWB + ((lane >> 4) << 4);
    const uint32_t bBase = sbase + A_BYTES + (wn * 64 + (lane & 15)) * ROWB + ((lane >> 4) << 4);

    float acc[4][8][4];
    #pragma unroll
    for (int mi = 0; mi < 4; mi++)
        #pragma unroll
        for (int ni = 0; ni < 8; ni++)
            #pragma unroll
            for (int r = 0; r < 4; r++) acc[mi][ni][r] = 0.0f;

    const int KT = K_IN / BK;  // 64
    load_stage(0 * STG_B);
    load_stage(1 * STG_B);
    load_stage(2 * STG_B);

    for (int kb = 0; kb < KT / NSTG; kb++) {       // 16 outer trips
        #pragma unroll
        for (int s = 0; s < NSTG; s++) {           // stage offset is constant
            const int kt = kb * NSTG + s;
            asm volatile("cp.async.wait_group %0;" :: "n"(2));
            __syncthreads();

            if (kt + 3 < KT) load_stage(((s + 3) & 3) * STG_B);
            else             asm volatile("cp.async.commit_group;");

            const uint32_t aOff = aBase + s * STG_B;
            const uint32_t bOff = bBase + s * STG_B;

            #pragma unroll
            for (int ks = 0; ks < 4; ks++) {
                uint32_t aF[4][4];
                #pragma unroll
                for (int mi = 0; mi < 4; mi++)
                    LDSM4(aF[mi][0], aF[mi][1], aF[mi][2], aF[mi][3],
                          aOff + mi * MI_STEP + ks * 32);
                #pragma unroll
                for (int p = 0; p < 4; p++) {
                    uint32_t b0, b1, b2, b3;
                    LDSM4(b0, b1, b2, b3, bOff + p * MI_STEP + ks * 32);
                    #pragma unroll
                    for (int mi = 0; mi < 4; mi++) {
                        MMA16816(acc[mi][2 * p],     aF[mi][0], aF[mi][1],
                                 aF[mi][2], aF[mi][3], b0, b2);
                        MMA16816(acc[mi][2 * p + 1], aF[mi][0], aF[mi][1],
                                 aF[mi][2], aF[mi][3], b1, b3);
                    }
                }
            }
            __syncthreads();
        }
    }

    // Epilogue: bias (from smem) + fp32 stores
    const size_t rowbase = (size_t)bm * BM + wm * 64 + (lane >> 2);
    const int coll = wn * 64 + (lane & 3) * 2;
    float* Cb = C + (size_t)bn * BN + coll;
    #pragma unroll
    for (int ni = 0; ni < 8; ni++) {
        const float bb0 = sBias[coll + ni * 8];
        const float bb1 = sBias[coll + ni * 8 + 1];
        #pragma unroll
        for (int mi = 0; mi < 4; mi++) {
            const size_t r0 = rowbase + mi * 16;
            float2 v0 = make_float2(acc[mi][ni][0] + bb0, acc[mi][ni][1] + bb1);
            float2 v1 = make_float2(acc[mi][ni][2] + bb0, acc[mi][ni][3] + bb1);
            *(float2*)&Cb[r0 * N_OUT + ni * 8]       = v0;
            *(float2*)&Cb[(r0 + 8) * N_OUT + ni * 8] = v1;
        }
    }
}

// ---------------------------------------------------------------------------
extern "C" void kernel_launch(void* const* d_in, const int* in_sizes, int n_in,
                              void* d_out, int out_size) {
    const float* x    = (const float*)d_in[0];   // [T, K] fp32
    const float* w    = (const float*)d_in[1];   // [N, K] fp32
    const float* bias = (const float*)d_in[2];   // [N]    fp32
    float* out = (float*)d_out;                  // [T, N] fp32

    __nv_bfloat16 *xq, *wq;
    cudaGetSymbolAddress((void**)&xq, g_xq);
    cudaGetSymbolAddress((void**)&wq, g_wq);

    rotate_quant_kernel<<<(int)(TGRP / 256), 256>>>(
        (const float4*)x, (const float4*)w, (uint4*)xq, (uint4*)wq);

    cudaFuncSetAttribute(gemm_bf16_kernel,
                         cudaFuncAttributeMaxDynamicSharedMemorySize, SMEM_BYTES);
    dim3 grid(N_OUT / BN, T_TOK / BM);
    gemm_bf16_kernel<<<grid, 256, SMEM_BYTES>>>(xq, wq, bias, out);
}

// round 6
// speedup vs baseline: 1.0463x; 1.0463x over previous
#include <cuda_runtime.h>
#include <cuda_bf16.h>
#include <cstdint>

// Problem shape (fixed by the dataset)
#define T_TOK 8192
#define K_IN  4096
#define N_OUT 4096
#define GROUP 32

// Dequantized scratch (bf16 is exact for MXFP4 values)
__device__ __nv_bfloat16 g_xq[(size_t)T_TOK * K_IN];   // 64 MB
__device__ __nv_bfloat16 g_wq[(size_t)N_OUT * K_IN];   // 32 MB

// ---------------------------------------------------------------------------
// Kernel 1: Hadamard rotate + MXFP4 qdq. One thread per 32-elem group,
// FWHT fully in registers, 8x LDG.128 in, 4x STG.128 out.
// ---------------------------------------------------------------------------
#define XGRP ((long long)T_TOK * K_IN / GROUP)
#define TGRP (XGRP + (long long)N_OUT * K_IN / GROUP)

__global__ __launch_bounds__(256)
void rotate_quant_kernel(const float4* __restrict__ x4,
                         const float4* __restrict__ w4,
                         uint4* __restrict__ xq4,
                         uint4* __restrict__ wq4) {
    long long g = (long long)blockIdx.x * blockDim.x + threadIdx.x;
    if (g >= TGRP) return;

    const float4* src;
    uint4* dst;
    if (g < XGRP) { src = x4 + g * 8;          dst = xq4 + g * 4; }
    else          { src = w4 + (g - XGRP) * 8; dst = wq4 + (g - XGRP) * 4; }

    float v[32];
    #pragma unroll
    for (int i = 0; i < 8; i++) {
        float4 t = src[i];
        v[4 * i] = t.x; v[4 * i + 1] = t.y; v[4 * i + 2] = t.z; v[4 * i + 3] = t.w;
    }

    #pragma unroll
    for (int st = 1; st < 32; st <<= 1) {
        #pragma unroll
        for (int i = 0; i < 32; i++) {
            if (!(i & st)) {
                float a = v[i], b = v[i | st];
                v[i] = a + b; v[i | st] = a - b;
            }
        }
    }
    const float c = 0.17677669529663688f;   // 1/sqrt(32)
    float amax = 0.0f;
    #pragma unroll
    for (int i = 0; i < 32; i++) { v[i] *= c; amax = fmaxf(amax, fabsf(v[i])); }
    amax = fmaxf(amax, 1.1754943508222875e-38f);

    int e = (int)((__float_as_uint(amax) >> 23) & 0xFF) - 127 - 2;
    e = max(-127, min(127, e));
    const float scale  = ldexpf(1.0f, e);
    const float iscale = ldexpf(1.0f, -e);

    uint32_t wbuf[16];
    #pragma unroll
    for (int i = 0; i < 32; i += 2) {
        uint32_t pk = 0;
        #pragma unroll
        for (int r = 0; r < 2; r++) {
            float s = v[i + r] * iscale;
            float a = fminf(fabsf(s), 6.0f);
            float q;
            if (a > 2.5f)       q = (a > 5.0f)  ? 6.0f : ((a > 3.5f)  ? 4.0f : 3.0f);
            else if (a > 1.25f) q = (a > 1.75f) ? 2.0f : 1.5f;
            else                q = (a > 0.75f) ? 1.0f : ((a > 0.25f) ? 0.5f : 0.0f);
            float res = copysignf(q, s) * scale;
            pk |= (uint32_t)__bfloat16_as_ushort(__float2bfloat16(res)) << (16 * r);
        }
        wbuf[i >> 1] = pk;
    }
    #pragma unroll
    for (int i = 0; i < 4; i++)
        dst[i] = make_uint4(wbuf[4 * i], wbuf[4 * i + 1], wbuf[4 * i + 2], wbuf[4 * i + 3]);
}

// ---------------------------------------------------------------------------
// Kernel 2: bf16 GEMM  C[M,N] = A[M,K] @ B[N,K]^T + bias, fp32 accumulate.
// 128x256 CTA tile, 512 threads (16 warps, 4x4), warp tile 32x64.
// BK=64 (128B rows), 4-stage cp.async (unrolled stage loop, constant
// offsets), ldmatrix.x4, A-frag + B-frag register double-buffering.
// ---------------------------------------------------------------------------
#define BM 128
#define BN 256
#define BK 64
#define NSTG 4
#define LDE 72                          // bf16 per smem row (16B pad)
#define ROWB (LDE * 2)                  // 144 bytes
#define A_BYTES (BM * ROWB)             // 18432
#define B_BYTES (BN * ROWB)             // 36864
#define STG_B (A_BYTES + B_BYTES)       // 55296
#define MI_STEP (16 * ROWB)             // 2304 bytes per 16 rows
#define SMEM_BYTES (NSTG * STG_B + 1024)

__device__ __forceinline__ uint32_t smem_u32(const void* p) {
    uint32_t a;
    asm("{ .reg .u64 t; cvta.to.shared.u64 t, %1; cvt.u32.u64 %0, t; }"
        : "=r"(a) : "l"(p));
    return a;
}
#define LDSM4(r0, r1, r2, r3, addr)                                           \
    asm volatile("ldmatrix.sync.aligned.m8n8.x4.shared.b16 {%0,%1,%2,%3}, [%4];" \
                 : "=r"(r0), "=r"(r1), "=r"(r2), "=r"(r3) : "r"(addr))
#define MMA16816(c, a0, a1, a2, a3, b0, b1)                                   \
    asm volatile("mma.sync.aligned.m16n8k16.row.col.f32.bf16.bf16.f32 "       \
                 "{%0,%1,%2,%3},{%4,%5,%6,%7},{%8,%9},{%0,%1,%2,%3};"          \
                 : "+f"(c[0]), "+f"(c[1]), "+f"(c[2]), "+f"(c[3])              \
                 : "r"(a0), "r"(a1), "r"(a2), "r"(a3), "r"(b0), "r"(b1))

__global__ __launch_bounds__(512, 1)
void gemm_bf16_kernel(const __nv_bfloat16* __restrict__ A,
                      const __nv_bfloat16* __restrict__ B,
                      const float* __restrict__ bias,
                      float* __restrict__ C) {
    extern __shared__ char smem[];
    const uint32_t sbase = smem_u32(smem);
    float* sBias = (float*)(smem + NSTG * STG_B);

    const int tid = threadIdx.x;
    const int bm = blockIdx.y, bn = blockIdx.x;
    const int warp = tid >> 5, lane = tid & 31;
    const int wm = warp & 3;            // 0..3, 32 rows
    const int wn = warp >> 2;           // 0..3, 64 cols

    if (tid < 256) sBias[tid] = bias[bn * BN + tid];

    // --- cp.async task setup: 6 x 16B per thread per stage ---
    const __nv_bfloat16* Ab = A + (size_t)bm * BM * K_IN;
    const __nv_bfloat16* Bb = B + (size_t)bn * BN * K_IN;
    uint32_t dA[2]; const char* sAp[2];
    #pragma unroll
    for (int i = 0; i < 2; i++) {
        int idx = tid + i * 512;        // 0..1023
        int row = idx >> 3, cc = idx & 7;
        dA[i] = row * ROWB + cc * 16;
        sAp[i] = (const char*)(Ab + (size_t)row * K_IN) + cc * 16;
    }
    uint32_t dB[4]; const char* sBp[4];
    #pragma unroll
    for (int j = 0; j < 4; j++) {
        int idx = tid + j * 512;        // 0..2047
        int row = idx >> 3, cc = idx & 7;
        dB[j] = A_BYTES + row * ROWB + cc * 16;
        sBp[j] = (const char*)(Bb + (size_t)row * K_IN) + cc * 16;
    }

    auto load_stage = [&](uint32_t off) {
        uint32_t base = sbase + off;
        #pragma unroll
        for (int i = 0; i < 2; i++) {
            asm volatile("cp.async.cg.shared.global [%0], [%1], 16;"
                         :: "r"(base + dA[i]), "l"(sAp[i]));
            sAp[i] += BK * 2;
        }
        #pragma unroll
        for (int j = 0; j < 4; j++) {
            asm volatile("cp.async.cg.shared.global [%0], [%1], 16;"
                         :: "r"(base + dB[j]), "l"(sBp[j]));
            sBp[j] += BK * 2;
        }
        asm volatile("cp.async.commit_group;");
    };

    // --- fragment base addresses (stage offset added as compile-time const) ---
    const uint32_t aBase = sbase + (wm * 32 + (lane & 15)) * ROWB + ((lane >> 4) << 4);
    const uint32_t bBase = sbase + A_BYTES + (wn * 64 + (lane & 15)) * ROWB + ((lane >> 4) << 4);

    float acc[2][8][4];
    #pragma unroll
    for (int mi = 0; mi < 2; mi++)
        #pragma unroll
        for (int ni = 0; ni < 8; ni++)
            #pragma unroll
            for (int r = 0; r < 4; r++) acc[mi][ni][r] = 0.0f;

    const int KT = K_IN / BK;  // 64
    load_stage(0 * STG_B);
    load_stage(1 * STG_B);
    load_stage(2 * STG_B);

    for (int kb = 0; kb < KT / NSTG; kb++) {       // 16 outer trips
        #pragma unroll
        for (int s = 0; s < NSTG; s++) {
            const int kt = kb * NSTG + s;
            asm volatile("cp.async.wait_group %0;" :: "n"(2));
            __syncthreads();

            if (kt + 3 < KT) load_stage(((s + 3) & 3) * STG_B);
            else             asm volatile("cp.async.commit_group;");

            const uint32_t aOff = aBase + s * STG_B;
            const uint32_t bOff = bBase + s * STG_B;

            // Prime: A frags for ks=0 (both mi), B frag for (ks=0, p=0)
            uint32_t aF[2][2][4];        // [buf][mi][reg]
            uint32_t bF[2][4];           // [buf][reg]
            LDSM4(aF[0][0][0], aF[0][0][1], aF[0][0][2], aF[0][0][3], aOff);
            LDSM4(aF[0][1][0], aF[0][1][1], aF[0][1][2], aF[0][1][3], aOff + MI_STEP);
            LDSM4(bF[0][0], bF[0][1], bF[0][2], bF[0][3], bOff);

            #pragma unroll
            for (int ks = 0; ks < 4; ks++) {
                const int ab = ks & 1;
                if (ks < 3) {            // prefetch A frags for ks+1
                    LDSM4(aF[ab ^ 1][0][0], aF[ab ^ 1][0][1],
                          aF[ab ^ 1][0][2], aF[ab ^ 1][0][3],
                          aOff + (ks + 1) * 32);
                    LDSM4(aF[ab ^ 1][1][0], aF[ab ^ 1][1][1],
                          aF[ab ^ 1][1][2], aF[ab ^ 1][1][3],
                          aOff + MI_STEP + (ks + 1) * 32);
                }
                #pragma unroll
                for (int p = 0; p < 4; p++) {
                    const int bb = p & 1;
                    // prefetch next B frag: p+1 of this ks, or p=0 of ks+1
                    if (p < 3)
                        LDSM4(bF[bb ^ 1][0], bF[bb ^ 1][1], bF[bb ^ 1][2], bF[bb ^ 1][3],
                              bOff + (p + 1) * MI_STEP + ks * 32);
                    else if (ks < 3)
                        LDSM4(bF[bb ^ 1][0], bF[bb ^ 1][1], bF[bb ^ 1][2], bF[bb ^ 1][3],
                              bOff + (ks + 1) * 32);
                    #pragma unroll
                    for (int mi = 0; mi < 2; mi++) {
                        MMA16816(acc[mi][2 * p],     aF[ab][mi][0], aF[ab][mi][1],
                                 aF[ab][mi][2], aF[ab][mi][3], bF[bb][0], bF[bb][2]);
                        MMA16816(acc[mi][2 * p + 1], aF[ab][mi][0], aF[ab][mi][1],
                                 aF[ab][mi][2], aF[ab][mi][3], bF[bb][1], bF[bb][3]);
                    }
                }
            }
        }
    }

    // Epilogue: bias (from smem) + fp32 stores
    const size_t rowbase = (size_t)bm * BM + wm * 32 + (lane >> 2);
    const int coll = wn * 64 + (lane & 3) * 2;
    float* Cb = C + (size_t)bn * BN + coll;
    #pragma unroll
    for (int ni = 0; ni < 8; ni++) {
        const float bb0 = sBias[coll + ni * 8];
        const float bb1 = sBias[coll + ni * 8 + 1];
        #pragma unroll
        for (int mi = 0; mi < 2; mi++) {
            const size_t r0 = rowbase + mi * 16;
            float2 v0 = make_float2(acc[mi][ni][0] + bb0, acc[mi][ni][1] + bb1);
            float2 v1 = make_float2(acc[mi][ni][2] + bb0, acc[mi][ni][3] + bb1);
            *(float2*)&Cb[r0 * N_OUT + ni * 8]       = v0;
            *(float2*)&Cb[(r0 + 8) * N_OUT + ni * 8] = v1;
        }
    }
}

// ---------------------------------------------------------------------------
extern "C" void kernel_launch(void* const* d_in, const int* in_sizes, int n_in,
                              void* d_out, int out_size) {
    const float* x    = (const float*)d_in[0];   // [T, K] fp32
    const float* w    = (const float*)d_in[1];   // [N, K] fp32
    const float* bias = (const float*)d_in[2];   // [N]    fp32
    float* out = (float*)d_out;                  // [T, N] fp32

    __nv_bfloat16 *xq, *wq;
    cudaGetSymbolAddress((void**)&xq, g_xq);
    cudaGetSymbolAddress((void**)&wq, g_wq);

    rotate_quant_kernel<<<(int)(TGRP / 256), 256>>>(
        (const float4*)x, (const float4*)w, (uint4*)xq, (uint4*)wq);

    cudaFuncSetAttribute(gemm_bf16_kernel,
                         cudaFuncAttributeMaxDynamicSharedMemorySize, SMEM_BYTES);
    dim3 grid(N_OUT / BN, T_TOK / BM);
    gemm_bf16_kernel<<<grid, 512, SMEM_BYTES>>>(xq, wq, bias, out);
}

// round 7
// speedup vs baseline: 1.0622x; 1.0153x over previous
#include <cuda_runtime.h>
#include <cuda_bf16.h>
#include <cstdint>

// Problem shape (fixed by the dataset)
#define T_TOK 8192
#define K_IN  4096
#define N_OUT 4096
#define GROUP 32

// Dequantized scratch (bf16 is exact for MXFP4 values)
__device__ __nv_bfloat16 g_xq[(size_t)T_TOK * K_IN];   // 64 MB
__device__ __nv_bfloat16 g_wq[(size_t)N_OUT * K_IN];   // 32 MB

// ---------------------------------------------------------------------------
// Kernel 1: Hadamard rotate + MXFP4 qdq. One thread per 32-elem group,
// FWHT fully in registers, 8x LDG.128 in, 4x STG.128 out.
// ---------------------------------------------------------------------------
#define XGRP ((long long)T_TOK * K_IN / GROUP)
#define TGRP (XGRP + (long long)N_OUT * K_IN / GROUP)

__global__ __launch_bounds__(256)
void rotate_quant_kernel(const float4* __restrict__ x4,
                         const float4* __restrict__ w4,
                         uint4* __restrict__ xq4,
                         uint4* __restrict__ wq4) {
    long long g = (long long)blockIdx.x * blockDim.x + threadIdx.x;
    if (g >= TGRP) return;

    const float4* src;
    uint4* dst;
    if (g < XGRP) { src = x4 + g * 8;          dst = xq4 + g * 4; }
    else          { src = w4 + (g - XGRP) * 8; dst = wq4 + (g - XGRP) * 4; }

    float v[32];
    #pragma unroll
    for (int i = 0; i < 8; i++) {
        float4 t = src[i];
        v[4 * i] = t.x; v[4 * i + 1] = t.y; v[4 * i + 2] = t.z; v[4 * i + 3] = t.w;
    }

    #pragma unroll
    for (int st = 1; st < 32; st <<= 1) {
        #pragma unroll
        for (int i = 0; i < 32; i++) {
            if (!(i & st)) {
                float a = v[i], b = v[i | st];
                v[i] = a + b; v[i | st] = a - b;
            }
        }
    }
    const float c = 0.17677669529663688f;   // 1/sqrt(32)
    float amax = 0.0f;
    #pragma unroll
    for (int i = 0; i < 32; i++) { v[i] *= c; amax = fmaxf(amax, fabsf(v[i])); }
    amax = fmaxf(amax, 1.1754943508222875e-38f);

    int e = (int)((__float_as_uint(amax) >> 23) & 0xFF) - 127 - 2;
    e = max(-127, min(127, e));
    const float scale  = ldexpf(1.0f, e);
    const float iscale = ldexpf(1.0f, -e);

    uint32_t wbuf[16];
    #pragma unroll
    for (int i = 0; i < 32; i += 2) {
        uint32_t pk = 0;
        #pragma unroll
        for (int r = 0; r < 2; r++) {
            float s = v[i + r] * iscale;
            float a = fminf(fabsf(s), 6.0f);
            float q;
            if (a > 2.5f)       q = (a > 5.0f)  ? 6.0f : ((a > 3.5f)  ? 4.0f : 3.0f);
            else if (a > 1.25f) q = (a > 1.75f) ? 2.0f : 1.5f;
            else                q = (a > 0.75f) ? 1.0f : ((a > 0.25f) ? 0.5f : 0.0f);
            float res = copysignf(q, s) * scale;
            pk |= (uint32_t)__bfloat16_as_ushort(__float2bfloat16(res)) << (16 * r);
        }
        wbuf[i >> 1] = pk;
    }
    #pragma unroll
    for (int i = 0; i < 4; i++)
        dst[i] = make_uint4(wbuf[4 * i], wbuf[4 * i + 1], wbuf[4 * i + 2], wbuf[4 * i + 3]);
}

// ---------------------------------------------------------------------------
// Kernel 2: bf16 GEMM  C[M,N] = A[M,K] @ B[N,K]^T + bias, fp32 accumulate.
// 128x128 CTA tile, 256 threads (8 warps, 4x2), warp tile 32x64,
// 2 CTAs per SM (overlaps pipeline/barrier bubbles across CTAs).
// BK=64 (128B rows), 3-stage cp.async, ldmatrix.x4 + reg double-buffering.
// ---------------------------------------------------------------------------
#define BM 128
#define BN 128
#define BK 64
#define NSTG 3
#define LDE 72                          // bf16 per smem row (16B pad)
#define ROWB (LDE * 2)                  // 144 bytes
#define A_BYTES (BM * ROWB)             // 18432
#define B_BYTES (BN * ROWB)             // 18432
#define STG_B (A_BYTES + B_BYTES)       // 36864
#define MI_STEP (16 * ROWB)             // 2304 bytes per 16 rows
#define SMEM_BYTES (NSTG * STG_B + 512) // 111104

__device__ __forceinline__ uint32_t smem_u32(const void* p) {
    uint32_t a;
    asm("{ .reg .u64 t; cvta.to.shared.u64 t, %1; cvt.u32.u64 %0, t; }"
        : "=r"(a) : "l"(p));
    return a;
}
#define LDSM4(r0, r1, r2, r3, addr)                                           \
    asm volatile("ldmatrix.sync.aligned.m8n8.x4.shared.b16 {%0,%1,%2,%3}, [%4];" \
                 : "=r"(r0), "=r"(r1), "=r"(r2), "=r"(r3) : "r"(addr))
#define MMA16816(c, a0, a1, a2, a3, b0, b1)                                   \
    asm volatile("mma.sync.aligned.m16n8k16.row.col.f32.bf16.bf16.f32 "       \
                 "{%0,%1,%2,%3},{%4,%5,%6,%7},{%8,%9},{%0,%1,%2,%3};"          \
                 : "+f"(c[0]), "+f"(c[1]), "+f"(c[2]), "+f"(c[3])              \
                 : "r"(a0), "r"(a1), "r"(a2), "r"(a3), "r"(b0), "r"(b1))

__global__ __launch_bounds__(256, 2)
void gemm_bf16_kernel(const __nv_bfloat16* __restrict__ A,
                      const __nv_bfloat16* __restrict__ B,
                      const float* __restrict__ bias,
                      float* __restrict__ C) {
    extern __shared__ char smem[];
    const uint32_t sbase = smem_u32(smem);
    float* sBias = (float*)(smem + NSTG * STG_B);

    const int tid = threadIdx.x;
    const int bm = blockIdx.y, bn = blockIdx.x;
    const int warp = tid >> 5, lane = tid & 31;
    const int wm = warp & 3;            // 0..3, 32 rows
    const int wn = warp >> 2;           // 0..1, 64 cols

    if (tid < 128) sBias[tid] = bias[bn * BN + tid];

    // --- cp.async task setup: 8 x 16B per thread per stage ---
    const __nv_bfloat16* Ab = A + (size_t)bm * BM * K_IN;
    const __nv_bfloat16* Bb = B + (size_t)bn * BN * K_IN;
    uint32_t dA[4]; const char* sAp[4];
    uint32_t dB[4]; const char* sBp[4];
    #pragma unroll
    for (int i = 0; i < 4; i++) {
        int idx = tid + i * 256;        // 0..1023
        int row = idx >> 3, cc = idx & 7;
        dA[i] = row * ROWB + cc * 16;
        sAp[i] = (const char*)(Ab + (size_t)row * K_IN) + cc * 16;
        dB[i] = A_BYTES + row * ROWB + cc * 16;
        sBp[i] = (const char*)(Bb + (size_t)row * K_IN) + cc * 16;
    }

    auto load_stage = [&](uint32_t off) {
        uint32_t base = sbase + off;
        #pragma unroll
        for (int i = 0; i < 4; i++) {
            asm volatile("cp.async.cg.shared.global [%0], [%1], 16;"
                         :: "r"(base + dA[i]), "l"(sAp[i]));
            sAp[i] += BK * 2;
            asm volatile("cp.async.cg.shared.global [%0], [%1], 16;"
                         :: "r"(base + dB[i]), "l"(sBp[i]));
            sBp[i] += BK * 2;
        }
        asm volatile("cp.async.commit_group;");
    };

    // --- fragment base addresses (hoisted) ---
    const uint32_t aBase = sbase + (wm * 32 + (lane & 15)) * ROWB + ((lane >> 4) << 4);
    const uint32_t bBase = sbase + A_BYTES + (wn * 64 + (lane & 15)) * ROWB + ((lane >> 4) << 4);

    float acc[2][8][4];
    #pragma unroll
    for (int mi = 0; mi < 2; mi++)
        #pragma unroll
        for (int ni = 0; ni < 8; ni++)
            #pragma unroll
            for (int r = 0; r < 4; r++) acc[mi][ni][r] = 0.0f;

    const int KT = K_IN / BK;  // 64
    load_stage(0 * STG_B);
    load_stage(1 * STG_B);
    uint32_t cOff = 0, lOff = 2 * STG_B;

    for (int kt = 0; kt < KT; kt++) {
        asm volatile("cp.async.wait_group %0;" :: "n"(1));
        __syncthreads();

        if (kt + 2 < KT) {
            load_stage(lOff);
            lOff += STG_B; if (lOff == NSTG * STG_B) lOff = 0;
        } else {
            asm volatile("cp.async.commit_group;");
        }

        const uint32_t aOff = aBase + cOff;
        const uint32_t bOff = bBase + cOff;
        cOff += STG_B; if (cOff == NSTG * STG_B) cOff = 0;

        // Prime: A frags for ks=0 (both mi), B frag for (ks=0, p=0)
        uint32_t aF[2][2][4];        // [buf][mi][reg]
        uint32_t bF[2][4];           // [buf][reg]
        LDSM4(aF[0][0][0], aF[0][0][1], aF[0][0][2], aF[0][0][3], aOff);
        LDSM4(aF[0][1][0], aF[0][1][1], aF[0][1][2], aF[0][1][3], aOff + MI_STEP);
        LDSM4(bF[0][0], bF[0][1], bF[0][2], bF[0][3], bOff);

        #pragma unroll
        for (int ks = 0; ks < 4; ks++) {
            const int ab = ks & 1;
            if (ks < 3) {            // prefetch A frags for ks+1
                LDSM4(aF[ab ^ 1][0][0], aF[ab ^ 1][0][1],
                      aF[ab ^ 1][0][2], aF[ab ^ 1][0][3],
                      aOff + (ks + 1) * 32);
                LDSM4(aF[ab ^ 1][1][0], aF[ab ^ 1][1][1],
                      aF[ab ^ 1][1][2], aF[ab ^ 1][1][3],
                      aOff + MI_STEP + (ks + 1) * 32);
            }
            #pragma unroll
            for (int p = 0; p < 4; p++) {
                const int bb = p & 1;
                if (p < 3)
                    LDSM4(bF[bb ^ 1][0], bF[bb ^ 1][1], bF[bb ^ 1][2], bF[bb ^ 1][3],
                          bOff + (p + 1) * MI_STEP + ks * 32);
                else if (ks < 3)
                    LDSM4(bF[bb ^ 1][0], bF[bb ^ 1][1], bF[bb ^ 1][2], bF[bb ^ 1][3],
                          bOff + (ks + 1) * 32);
                #pragma unroll
                for (int mi = 0; mi < 2; mi++) {
                    MMA16816(acc[mi][2 * p],     aF[ab][mi][0], aF[ab][mi][1],
                             aF[ab][mi][2], aF[ab][mi][3], bF[bb][0], bF[bb][2]);
                    MMA16816(acc[mi][2 * p + 1], aF[ab][mi][0], aF[ab][mi][1],
                             aF[ab][mi][2], aF[ab][mi][3], bF[bb][1], bF[bb][3]);
                }
            }
        }
    }

    // Epilogue: bias (from smem) + fp32 stores
    const size_t rowbase = (size_t)bm * BM + wm * 32 + (lane >> 2);
    const int coll = wn * 64 + (lane & 3) * 2;
    float* Cb = C + (size_t)bn * BN + coll;
    #pragma unroll
    for (int ni = 0; ni < 8; ni++) {
        const float bb0 = sBias[coll + ni * 8];
        const float bb1 = sBias[coll + ni * 8 + 1];
        #pragma unroll
        for (int mi = 0; mi < 2; mi++) {
            const size_t r0 = rowbase + mi * 16;
            float2 v0 = make_float2(acc[mi][ni][0] + bb0, acc[mi][ni][1] + bb1);
            float2 v1 = make_float2(acc[mi][ni][2] + bb0, acc[mi][ni][3] + bb1);
            *(float2*)&Cb[r0 * N_OUT + ni * 8]       = v0;
            *(float2*)&Cb[(r0 + 8) * N_OUT + ni * 8] = v1;
        }
    }
}

// ---------------------------------------------------------------------------
extern "C" void kernel_launch(void* const* d_in, const int* in_sizes, int n_in,
                              void* d_out, int out_size) {
    const float* x    = (const float*)d_in[0];   // [T, K] fp32
    const float* w    = (const float*)d_in[1];   // [N, K] fp32
    const float* bias = (const float*)d_in[2];   // [N]    fp32
    float* out = (float*)d_out;                  // [T, N] fp32

    __nv_bfloat16 *xq, *wq;
    cudaGetSymbolAddress((void**)&xq, g_xq);
    cudaGetSymbolAddress((void**)&wq, g_wq);

    rotate_quant_kernel<<<(int)(TGRP / 256), 256>>>(
        (const float4*)x, (const float4*)w, (uint4*)xq, (uint4*)wq);

    cudaFuncSetAttribute(gemm_bf16_kernel,
                         cudaFuncAttributeMaxDynamicSharedMemorySize, SMEM_BYTES);
    dim3 grid(N_OUT / BN, T_TOK / BM);
    gemm_bf16_kernel<<<grid, 256, SMEM_BYTES>>>(xq, wq, bias, out);
}

// round 8
// speedup vs baseline: 1.2974x; 1.2214x over previous
#include <cuda_runtime.h>
#include <cuda_bf16.h>
#include <cstdint>

// Problem shape (fixed by the dataset)
#define T_TOK 8192
#define K_IN  4096
#define N_OUT 4096
#define GROUP 32

// Dequantized scratch (bf16 is exact for MXFP4 values)
__device__ __nv_bfloat16 g_xq[(size_t)T_TOK * K_IN];   // 64 MB
__device__ __nv_bfloat16 g_wq[(size_t)N_OUT * K_IN];   // 32 MB

// ---------------------------------------------------------------------------
// Kernel 1: Hadamard rotate + MXFP4 qdq. One thread per 32-elem group,
// FWHT fully in registers, 8x LDG.128 in, 4x STG.128 out.
// ---------------------------------------------------------------------------
#define XGRP ((long long)T_TOK * K_IN / GROUP)
#define TGRP (XGRP + (long long)N_OUT * K_IN / GROUP)

__global__ __launch_bounds__(256)
void rotate_quant_kernel(const float4* __restrict__ x4,
                         const float4* __restrict__ w4,
                         uint4* __restrict__ xq4,
                         uint4* __restrict__ wq4) {
    long long g = (long long)blockIdx.x * blockDim.x + threadIdx.x;
    if (g >= TGRP) return;

    const float4* src;
    uint4* dst;
    if (g < XGRP) { src = x4 + g * 8;          dst = xq4 + g * 4; }
    else          { src = w4 + (g - XGRP) * 8; dst = wq4 + (g - XGRP) * 4; }

    float v[32];
    #pragma unroll
    for (int i = 0; i < 8; i++) {
        float4 t = src[i];
        v[4 * i] = t.x; v[4 * i + 1] = t.y; v[4 * i + 2] = t.z; v[4 * i + 3] = t.w;
    }

    #pragma unroll
    for (int st = 1; st < 32; st <<= 1) {
        #pragma unroll
        for (int i = 0; i < 32; i++) {
            if (!(i & st)) {
                float a = v[i], b = v[i | st];
                v[i] = a + b; v[i | st] = a - b;
            }
        }
    }
    const float c = 0.17677669529663688f;   // 1/sqrt(32)
    float amax = 0.0f;
    #pragma unroll
    for (int i = 0; i < 32; i++) { v[i] *= c; amax = fmaxf(amax, fabsf(v[i])); }
    amax = fmaxf(amax, 1.1754943508222875e-38f);

    int e = (int)((__float_as_uint(amax) >> 23) & 0xFF) - 127 - 2;
    e = max(-127, min(127, e));
    const float scale  = ldexpf(1.0f, e);
    const float iscale = ldexpf(1.0f, -e);

    uint32_t wbuf[16];
    #pragma unroll
    for (int i = 0; i < 32; i += 2) {
        uint32_t pk = 0;
        #pragma unroll
        for (int r = 0; r < 2; r++) {
            float s = v[i + r] * iscale;
            float a = fminf(fabsf(s), 6.0f);
            float q;
            if (a > 2.5f)       q = (a > 5.0f)  ? 6.0f : ((a > 3.5f)  ? 4.0f : 3.0f);
            else if (a > 1.25f) q = (a > 1.75f) ? 2.0f : 1.5f;
            else                q = (a > 0.75f) ? 1.0f : ((a > 0.25f) ? 0.5f : 0.0f);
            float res = copysignf(q, s) * scale;
            pk |= (uint32_t)__bfloat16_as_ushort(__float2bfloat16(res)) << (16 * r);
        }
        wbuf[i >> 1] = pk;
    }
    #pragma unroll
    for (int i = 0; i < 4; i++)
        dst[i] = make_uint4(wbuf[4 * i], wbuf[4 * i + 1], wbuf[4 * i + 2], wbuf[4 * i + 3]);
}

// ---------------------------------------------------------------------------
// Kernel 2: bf16 GEMM  C[M,N] = A[M,K] @ B[N,K]^T + bias, fp32 accumulate.
// 128x128 CTA tile, 256 threads (8 warps, 4x2), warp tile 32x64,
// 2 CTAs per SM. BK=64, 3-stage cp.async with the per-stage load split
// into 4 chunks interleaved into the k16 steps (keeps LDSM ahead of the
// cp.async burst in the l1tex FIFO). Stage loop unrolled x3 so smem slot
// offsets are compile-time immediates.
// ---------------------------------------------------------------------------
#define BM 128
#define BN 128
#define BK 64
#define NSTG 3
#define LDE 72                          // bf16 per smem row (16B pad)
#define ROWB (LDE * 2)                  // 144 bytes
#define A_BYTES (BM * ROWB)             // 18432
#define B_BYTES (BN * ROWB)             // 18432
#define STG_B (A_BYTES + B_BYTES)       // 36864
#define MI_STEP (16 * ROWB)             // 2304 bytes per 16 rows
#define SMEM_BYTES (NSTG * STG_B + 512) // 111104

__device__ __forceinline__ uint32_t smem_u32(const void* p) {
    uint32_t a;
    asm("{ .reg .u64 t; cvta.to.shared.u64 t, %1; cvt.u32.u64 %0, t; }"
        : "=r"(a) : "l"(p));
    return a;
}
#define LDSM4(r0, r1, r2, r3, addr)                                           \
    asm volatile("ldmatrix.sync.aligned.m8n8.x4.shared.b16 {%0,%1,%2,%3}, [%4];" \
                 : "=r"(r0), "=r"(r1), "=r"(r2), "=r"(r3) : "r"(addr))
#define MMA16816(c, a0, a1, a2, a3, b0, b1)                                   \
    asm volatile("mma.sync.aligned.m16n8k16.row.col.f32.bf16.bf16.f32 "       \
                 "{%0,%1,%2,%3},{%4,%5,%6,%7},{%8,%9},{%0,%1,%2,%3};"          \
                 : "+f"(c[0]), "+f"(c[1]), "+f"(c[2]), "+f"(c[3])              \
                 : "r"(a0), "r"(a1), "r"(a2), "r"(a3), "r"(b0), "r"(b1))
#define CPASYNC(dst, src)                                                     \
    asm volatile("cp.async.cg.shared.global [%0], [%1], 16;"                  \
                 :: "r"(dst), "l"(src))

__global__ __launch_bounds__(256, 2)
void gemm_bf16_kernel(const __nv_bfloat16* __restrict__ A,
                      const __nv_bfloat16* __restrict__ B,
                      const float* __restrict__ bias,
                      float* __restrict__ C) {
    extern __shared__ char smem[];
    const uint32_t sbase = smem_u32(smem);
    float* sBias = (float*)(smem + NSTG * STG_B);

    const int tid = threadIdx.x;
    const int bm = blockIdx.y, bn = blockIdx.x;
    const int warp = tid >> 5, lane = tid & 31;
    const int wm = warp & 3;            // 0..3, 32 rows
    const int wn = warp >> 2;           // 0..1, 64 cols

    if (tid < 128) sBias[tid] = bias[bn * BN + tid];

    // --- cp.async task setup: 8 x 16B per thread per stage (4 chunks) ---
    const __nv_bfloat16* Ab = A + (size_t)bm * BM * K_IN;
    const __nv_bfloat16* Bb = B + (size_t)bn * BN * K_IN;
    uint32_t dA[4]; const char* sAp[4];
    uint32_t dB[4]; const char* sBp[4];
    #pragma unroll
    for (int i = 0; i < 4; i++) {
        int idx = tid + i * 256;        // 0..1023
        int row = idx >> 3, cc = idx & 7;
        dA[i] = row * ROWB + cc * 16;
        sAp[i] = (const char*)(Ab + (size_t)row * K_IN) + cc * 16;
        dB[i] = A_BYTES + row * ROWB + cc * 16;
        sBp[i] = (const char*)(Bb + (size_t)row * K_IN) + cc * 16;
    }

    auto load_stage_full = [&](uint32_t off) {
        uint32_t base = sbase + off;
        #pragma unroll
        for (int i = 0; i < 4; i++) {
            CPASYNC(base + dA[i], sAp[i]); sAp[i] += BK * 2;
            CPASYNC(base + dB[i], sBp[i]); sBp[i] += BK * 2;
        }
        asm volatile("cp.async.commit_group;");
    };

    // --- fragment base addresses (hoisted) ---
    const uint32_t aBase = sbase + (wm * 32 + (lane & 15)) * ROWB + ((lane >> 4) << 4);
    const uint32_t bBase = sbase + A_BYTES + (wn * 64 + (lane & 15)) * ROWB + ((lane >> 4) << 4);

    float acc[2][8][4];
    #pragma unroll
    for (int mi = 0; mi < 2; mi++)
        #pragma unroll
        for (int ni = 0; ni < 8; ni++)
            #pragma unroll
            for (int r = 0; r < 4; r++) acc[mi][ni][r] = 0.0f;

    // Compute one stage (smem slot at compile-time offset cOffC); while
    // computing, optionally stream the next-next stage into slot lOffC,
    // one chunk (1 A + 1 B cp.async per thread) per k16 step.
    auto compute_stage = [&](uint32_t cOffC, uint32_t lOffC, bool doLoad) {
        const uint32_t aOff = aBase + cOffC;
        const uint32_t bOff = bBase + cOffC;
        const uint32_t lbase = sbase + lOffC;

        uint32_t aF[2][2][4];        // [buf][mi][reg]
        uint32_t bF[2][4];           // [buf][reg]
        LDSM4(aF[0][0][0], aF[0][0][1], aF[0][0][2], aF[0][0][3], aOff);
        LDSM4(aF[0][1][0], aF[0][1][1], aF[0][1][2], aF[0][1][3], aOff + MI_STEP);
        LDSM4(bF[0][0], bF[0][1], bF[0][2], bF[0][3], bOff);

        #pragma unroll
        for (int ks = 0; ks < 4; ks++) {
            const int ab = ks & 1;
            if (ks < 3) {            // prefetch A frags for ks+1
                LDSM4(aF[ab ^ 1][0][0], aF[ab ^ 1][0][1],
                      aF[ab ^ 1][0][2], aF[ab ^ 1][0][3],
                      aOff + (ks + 1) * 32);
                LDSM4(aF[ab ^ 1][1][0], aF[ab ^ 1][1][1],
                      aF[ab ^ 1][1][2], aF[ab ^ 1][1][3],
                      aOff + MI_STEP + (ks + 1) * 32);
            }
            if (doLoad) {            // one chunk of the next-next stage
                CPASYNC(lbase + dA[ks], sAp[ks]); sAp[ks] += BK * 2;
                CPASYNC(lbase + dB[ks], sBp[ks]); sBp[ks] += BK * 2;
            }
            #pragma unroll
            for (int p = 0; p < 4; p++) {
                const int bb = p & 1;
                if (p < 3)
                    LDSM4(bF[bb ^ 1][0], bF[bb ^ 1][1], bF[bb ^ 1][2], bF[bb ^ 1][3],
                          bOff + (p + 1) * MI_STEP + ks * 32);
                else if (ks < 3)
                    LDSM4(bF[bb ^ 1][0], bF[bb ^ 1][1], bF[bb ^ 1][2], bF[bb ^ 1][3],
                          bOff + (ks + 1) * 32);
                #pragma unroll
                for (int mi = 0; mi < 2; mi++) {
                    MMA16816(acc[mi][2 * p],     aF[ab][mi][0], aF[ab][mi][1],
                             aF[ab][mi][2], aF[ab][mi][3], bF[bb][0], bF[bb][2]);
                    MMA16816(acc[mi][2 * p + 1], aF[ab][mi][0], aF[ab][mi][1],
                             aF[ab][mi][2], aF[ab][mi][3], bF[bb][1], bF[bb][3]);
                }
            }
        }
    };

    const int KT = K_IN / BK;  // 64
    load_stage_full(0 * STG_B);
    load_stage_full(1 * STG_B);

    // Stages 0..62 (21 unrolled triples); stage kt lives in slot kt%3 == s.
    for (int kb = 0; kb < 21; kb++) {
        #pragma unroll
        for (int s = 0; s < 3; s++) {
            const int kt = kb * 3 + s;
            asm volatile("cp.async.wait_group %0;" :: "n"(1));
            __syncthreads();
            const bool doLoad = (kt + 2) < KT;
            const uint32_t cOffC = (uint32_t)(s * STG_B);
            const uint32_t lOffC = (uint32_t)(((s + 2) % 3) * STG_B);
            compute_stage(cOffC, lOffC, doLoad);
            asm volatile("cp.async.commit_group;");
        }
    }
    // Final stage 63 (slot 0)
    asm volatile("cp.async.wait_group %0;" :: "n"(0));
    __syncthreads();
    compute_stage(0, 0, false);

    // Epilogue: bias (from smem) + fp32 stores
    const size_t rowbase = (size_t)bm * BM + wm * 32 + (lane >> 2);
    const int coll = wn * 64 + (lane & 3) * 2;
    float* Cb = C + (size_t)bn * BN + coll;
    #pragma unroll
    for (int ni = 0; ni < 8; ni++) {
        const float bb0 = sBias[coll + ni * 8];
        const float bb1 = sBias[coll + ni * 8 + 1];
        #pragma unroll
        for (int mi = 0; mi < 2; mi++) {
            const size_t r0 = rowbase + mi * 16;
            float2 v0 = make_float2(acc[mi][ni][0] + bb0, acc[mi][ni][1] + bb1);
            float2 v1 = make_float2(acc[mi][ni][2] + bb0, acc[mi][ni][3] + bb1);
            *(float2*)&Cb[r0 * N_OUT + ni * 8]       = v0;
            *(float2*)&Cb[(r0 + 8) * N_OUT + ni * 8] = v1;
        }
    }
}

// ---------------------------------------------------------------------------
extern "C" void kernel_launch(void* const* d_in, const int* in_sizes, int n_in,
                              void* d_out, int out_size) {
    const float* x    = (const float*)d_in[0];   // [T, K] fp32
    const float* w    = (const float*)d_in[1];   // [N, K] fp32
    const float* bias = (const float*)d_in[2];   // [N]    fp32
    float* out = (float*)d_out;                  // [T, N] fp32

    __nv_bfloat16 *xq, *wq;
    cudaGetSymbolAddress((void**)&xq, g_xq);
    cudaGetSymbolAddress((void**)&wq, g_wq);

    rotate_quant_kernel<<<(int)(TGRP / 256), 256>>>(
        (const float4*)x, (const float4*)w, (uint4*)xq, (uint4*)wq);

    cudaFuncSetAttribute(gemm_bf16_kernel,
                         cudaFuncAttributeMaxDynamicSharedMemorySize, SMEM_BYTES);
    dim3 grid(N_OUT / BN, T_TOK / BM);
    gemm_bf16_kernel<<<grid, 256, SMEM_BYTES>>>(xq, wq, bias, out);
}